// round 1
// baseline (speedup 1.0000x reference)
#include <cuda_runtime.h>
#include <math.h>

// ---------------------------------------------------------------------------
// BFM factorization-machine scoring, sparsity-aware.
//   y = w0 + x·w_bias + u·t + t·b + 0.5*(b·b - sum_b_sq) + u·b ; out = sigmoid(y*delta)
// where u = x[:N] @ u_V, t = x[N:N+M] @ t_V, b = x[N+M:] @ b_V  (K = 64).
// x is sparse; zero entries contribute exactly nothing, so we compact nonzeros.
// ---------------------------------------------------------------------------

#define KDIM 64
#define SCAN_TPB 256
#define MAX_BLOCKS 8192
#define SORT_CAP 4096

// Scratch (static device globals: allocation-free)
__device__ int   g_nnz = 0;                 // reset at end of finish kernel
__device__ int   g_idx[2100000];
__device__ float g_val[2100000];
__device__ float g_bias_part[MAX_BLOCKS];

__global__ void bfm_scan_kernel(const float* __restrict__ x,
                                const float* __restrict__ wb,
                                int P4, int P)
{
    int i = blockIdx.x * blockDim.x + threadIdx.x;
    float bias = 0.f;

    if (i < P4) {
        float4 xv = reinterpret_cast<const float4*>(x)[i];
        float4 wv = reinterpret_cast<const float4*>(wb)[i];
        bias = xv.x * wv.x + xv.y * wv.y + xv.z * wv.z + xv.w * wv.w;
        int base = i * 4;
        if (xv.x != 0.f) { int p = atomicAdd(&g_nnz, 1); g_idx[p] = base + 0; g_val[p] = xv.x; }
        if (xv.y != 0.f) { int p = atomicAdd(&g_nnz, 1); g_idx[p] = base + 1; g_val[p] = xv.y; }
        if (xv.z != 0.f) { int p = atomicAdd(&g_nnz, 1); g_idx[p] = base + 2; g_val[p] = xv.z; }
        if (xv.w != 0.f) { int p = atomicAdd(&g_nnz, 1); g_idx[p] = base + 3; g_val[p] = xv.w; }
    }

    // tail (P not multiple of 4) handled by one thread
    if (blockIdx.x == 0 && threadIdx.x == 0) {
        for (int r = P4 * 4; r < P; ++r) {
            float xv = x[r];
            bias += xv * wb[r];
            if (xv != 0.f) { int p = atomicAdd(&g_nnz, 1); g_idx[p] = r; g_val[p] = xv; }
        }
    }

    // block-reduce bias
    __shared__ float sred[SCAN_TPB];
    sred[threadIdx.x] = bias;
    __syncthreads();
    for (int s = SCAN_TPB / 2; s > 0; s >>= 1) {
        if (threadIdx.x < s) sred[threadIdx.x] += sred[threadIdx.x + s];
        __syncthreads();
    }
    if (threadIdx.x == 0) g_bias_part[blockIdx.x] = sred[0];
}

__global__ void bfm_finish_kernel(const float* __restrict__ w0,
                                  const float* __restrict__ delta,
                                  const float* __restrict__ uV,
                                  const float* __restrict__ tV,
                                  const float* __restrict__ bV,
                                  float* __restrict__ out,
                                  int out_size, int nblocks, int N, int M)
{
    __shared__ float s_red[256];
    __shared__ float s_u[KDIM], s_t[KDIM], s_b[KDIM];
    __shared__ int   s_idx[SORT_CAP];
    __shared__ float s_val[SORT_CAP];
    const int tid = threadIdx.x;

    // ---- sum bias partials ----
    float bp = 0.f;
    for (int i = tid; i < nblocks; i += 256) bp += g_bias_part[i];
    s_red[tid] = bp;
    __syncthreads();
    for (int s = 128; s > 0; s >>= 1) {
        if (tid < s) s_red[tid] += s_red[tid + s];
        __syncthreads();
    }
    const float bias = s_red[0];
    __syncthreads();

    const int nnz = g_nnz;
    const bool in_smem = (nnz <= SORT_CAP);

    if (in_smem) {
        for (int i = tid; i < nnz; i += 256) { s_idx[i] = g_idx[i]; s_val[i] = g_val[i]; }
        __syncthreads();
        // odd-even transposition sort by index (determinism across replays)
        for (int phase = 0; phase < nnz; ++phase) {
            int start = phase & 1;
            for (int i = start + 2 * tid; i + 1 < nnz; i += 512) {
                if (s_idx[i] > s_idx[i + 1]) {
                    int ti = s_idx[i]; s_idx[i] = s_idx[i + 1]; s_idx[i + 1] = ti;
                    float tv = s_val[i]; s_val[i] = s_val[i + 1]; s_val[i + 1] = tv;
                }
            }
            __syncthreads();
        }
    }

    // ---- accumulate K=64 vectors; 4 groups of 64 lanes ----
    const int k = tid & (KDIM - 1);
    const int g = tid >> 6;
    float au = 0.f, at = 0.f, ab = 0.f, absq = 0.f;
    for (int j = g; j < nnz; j += 4) {
        int   idx;
        float v;
        if (in_smem) { idx = s_idx[j]; v = s_val[j]; }
        else         { idx = g_idx[j]; v = g_val[j]; }
        if (idx < N) {
            au += v * uV[(size_t)idx * KDIM + k];
        } else if (idx < N + M) {
            at += v * tV[(size_t)(idx - N) * KDIM + k];
        } else {
            float bv = bV[(size_t)(idx - N - M) * KDIM + k];
            ab   += v * bv;
            absq += v * bv * bv;
        }
    }
    __syncthreads();

    // fold 4 groups -> 64-lane vectors
    s_red[tid] = au; __syncthreads();
    if (tid < KDIM) s_u[tid] = s_red[tid] + s_red[tid + 64] + s_red[tid + 128] + s_red[tid + 192];
    __syncthreads();
    s_red[tid] = at; __syncthreads();
    if (tid < KDIM) s_t[tid] = s_red[tid] + s_red[tid + 64] + s_red[tid + 128] + s_red[tid + 192];
    __syncthreads();
    s_red[tid] = ab; __syncthreads();
    if (tid < KDIM) s_b[tid] = s_red[tid] + s_red[tid + 64] + s_red[tid + 128] + s_red[tid + 192];
    __syncthreads();

    // sum_b_sq scalar
    s_red[tid] = absq; __syncthreads();
    for (int s = 128; s > 0; s >>= 1) {
        if (tid < s) s_red[tid] += s_red[tid + s];
        __syncthreads();
    }
    const float sum_b_sq = s_red[0];
    __syncthreads();

    // combined interaction terms: u·t + t·b + u·b + 0.5*b·b  in one reduction
    float p = 0.f;
    if (tid < KDIM) {
        float uu = s_u[tid], tt = s_t[tid], bb = s_b[tid];
        p = uu * tt + tt * bb + uu * bb + 0.5f * bb * bb;
    }
    s_red[tid] = p;
    __syncthreads();
    for (int s = 128; s > 0; s >>= 1) {
        if (tid < s) s_red[tid] += s_red[tid + s];
        __syncthreads();
    }

    if (tid == 0) {
        float y = w0[0] + bias + s_red[0] - 0.5f * sum_b_sq;
        float z = y * delta[0];
        float r = 1.f / (1.f + expf(-z));
        for (int i = 0; i < out_size; ++i) out[i] = r;
        g_nnz = 0;  // reset for next replay (graph-capturable, deterministic)
    }
}

extern "C" void kernel_launch(void* const* d_in, const int* in_sizes, int n_in,
                              void* d_out, int out_size)
{
    const float* x     = (const float*)d_in[0];
    const float* delta = (const float*)d_in[1];
    /* pmi = d_in[2] unused */
    const float* w0    = (const float*)d_in[3];
    const float* wb    = (const float*)d_in[4];
    const float* uV    = (const float*)d_in[5];
    const float* tV    = (const float*)d_in[6];
    const float* bV    = (const float*)d_in[7];

    int P  = in_sizes[0];
    int N  = in_sizes[5] / KDIM;
    int M  = in_sizes[6] / KDIM;
    int P4 = P / 4;
    int blocks = (P4 + SCAN_TPB - 1) / SCAN_TPB;
    if (blocks > MAX_BLOCKS) blocks = MAX_BLOCKS;  // safety; not hit at P=2M

    bfm_scan_kernel<<<blocks, SCAN_TPB>>>(x, wb, P4, P);
    bfm_finish_kernel<<<1, 256>>>(w0, delta, uV, tV, bV,
                                  (float*)d_out, out_size, blocks, N, M);
}

// round 2
// speedup vs baseline: 1.8040x; 1.8040x over previous
#include <cuda_runtime.h>
#include <math.h>

// ---------------------------------------------------------------------------
// BFM factorization-machine scoring, sparsity-aware.
//   y = w0 + x·w_bias + u·t + t·b + 0.5*(b·b - sum_b_sq) + u·b ; out = sigmoid(y*delta)
// u = x[:N] @ u_V, t = x[N:N+M] @ t_V, b = x[N+M:] @ b_V  (K = 64), x sparse.
// Scan compacts nonzeros of x only (8 MB read); finish kernel rank-sorts the
// tiny nonzero list (determinism), gathers wb + embedding rows with all loads
// in flight, and reduces.
// ---------------------------------------------------------------------------

#define KDIM 64
#define SCAN_TPB 512
#define FIN_TPB 512
#define SORT_CAP 2048

__device__ int   g_nnz = 0;                 // reset at end of finish kernel
__device__ int   g_idx[2100000];
__device__ float g_val[2100000];

__global__ void bfm_scan_kernel(const float* __restrict__ x, int P4, int P)
{
    int i = blockIdx.x * blockDim.x + threadIdx.x;
    if (i < P4) {
        float4 xv = reinterpret_cast<const float4*>(x)[i];
        int base = i * 4;
        if (xv.x != 0.f) { int p = atomicAdd(&g_nnz, 1); g_idx[p] = base + 0; g_val[p] = xv.x; }
        if (xv.y != 0.f) { int p = atomicAdd(&g_nnz, 1); g_idx[p] = base + 1; g_val[p] = xv.y; }
        if (xv.z != 0.f) { int p = atomicAdd(&g_nnz, 1); g_idx[p] = base + 2; g_val[p] = xv.z; }
        if (xv.w != 0.f) { int p = atomicAdd(&g_nnz, 1); g_idx[p] = base + 3; g_val[p] = xv.w; }
    }
    if (blockIdx.x == 0 && threadIdx.x == 0) {
        for (int r = P4 * 4; r < P; ++r) {
            float xv = x[r];
            if (xv != 0.f) { int p = atomicAdd(&g_nnz, 1); g_idx[p] = r; g_val[p] = xv; }
        }
    }
}

__global__ void __launch_bounds__(FIN_TPB, 1)
bfm_finish_kernel(const float* __restrict__ w0,
                  const float* __restrict__ delta,
                  const float* __restrict__ wb,
                  const float* __restrict__ uV,
                  const float* __restrict__ tV,
                  const float* __restrict__ bV,
                  float* __restrict__ out,
                  int out_size, int N, int M)
{
    __shared__ float s_red[FIN_TPB];
    __shared__ float s_u[KDIM], s_t[KDIM], s_b[KDIM];
    __shared__ int   s_ri[SORT_CAP];   // raw indices
    __shared__ float s_rv[SORT_CAP];   // raw values
    __shared__ int   s_idx[SORT_CAP];  // sorted
    __shared__ float s_val[SORT_CAP];
    const int tid = threadIdx.x;

    const int nnz = g_nnz;
    const bool in_smem = (nnz <= SORT_CAP);

    if (in_smem) {
        for (int i = tid; i < nnz; i += FIN_TPB) { s_ri[i] = g_idx[i]; s_rv[i] = g_val[i]; }
        __syncthreads();
        // rank sort: indices are unique positions of x, so ranks are a permutation
        for (int i = tid; i < nnz; i += FIN_TPB) {
            int my = s_ri[i];
            int rank = 0;
            for (int j = 0; j < nnz; ++j) rank += (s_ri[j] < my);
            s_idx[rank] = my; s_val[rank] = s_rv[i];
        }
        __syncthreads();
    }

    // ---- bias = sum v * wb[idx] over sorted list (deterministic) ----
    float bp = 0.f;
    for (int i = tid; i < nnz; i += FIN_TPB) {
        int idx; float v;
        if (in_smem) { idx = s_idx[i]; v = s_val[i]; }
        else         { idx = g_idx[i]; v = g_val[i]; }
        bp += v * wb[idx];
    }
    s_red[tid] = bp;
    __syncthreads();
    for (int s = FIN_TPB / 2; s > 0; s >>= 1) {
        if (tid < s) s_red[tid] += s_red[tid + s];
        __syncthreads();
    }
    const float bias = s_red[0];
    __syncthreads();

    // ---- embedding gather: K=64 lanes x 8 row-groups, branchless ----
    const int k = tid & (KDIM - 1);
    const int g = tid >> 6;            // 0..7
    float au = 0.f, at_ = 0.f, ab = 0.f, absq = 0.f;
    #pragma unroll 4
    for (int j = g; j < nnz; j += 8) {
        int idx; float v;
        if (in_smem) { idx = s_idx[j]; v = s_val[j]; }
        else         { idx = g_idx[j]; v = g_val[j]; }
        bool isU = idx < N;
        bool isT = !isU && (idx < N + M);
        const float* p = isU ? (uV + (size_t)idx * KDIM)
                       : isT ? (tV + (size_t)(idx - N) * KDIM)
                             : (bV + (size_t)(idx - N - M) * KDIM);
        float e  = p[k];
        float ve = v * e;
        au   += isU ? ve : 0.f;
        at_  += isT ? ve : 0.f;
        ab   += (!isU && !isT) ? ve : 0.f;
        absq += (!isU && !isT) ? ve * e : 0.f;
    }
    __syncthreads();

    // fold 8 groups -> 64-lane vectors
    s_red[tid] = au; __syncthreads();
    if (tid < KDIM) { float s = 0.f;
        #pragma unroll
        for (int q = 0; q < 8; ++q) s += s_red[tid + 64 * q];
        s_u[tid] = s; }
    __syncthreads();
    s_red[tid] = at_; __syncthreads();
    if (tid < KDIM) { float s = 0.f;
        #pragma unroll
        for (int q = 0; q < 8; ++q) s += s_red[tid + 64 * q];
        s_t[tid] = s; }
    __syncthreads();
    s_red[tid] = ab; __syncthreads();
    if (tid < KDIM) { float s = 0.f;
        #pragma unroll
        for (int q = 0; q < 8; ++q) s += s_red[tid + 64 * q];
        s_b[tid] = s; }
    __syncthreads();

    // sum_b_sq scalar
    s_red[tid] = absq; __syncthreads();
    for (int s = FIN_TPB / 2; s > 0; s >>= 1) {
        if (tid < s) s_red[tid] += s_red[tid + s];
        __syncthreads();
    }
    const float sum_b_sq = s_red[0];
    __syncthreads();

    // combined interaction terms: u·t + t·b + u·b + 0.5*b·b in one reduction
    float p = 0.f;
    if (tid < KDIM) {
        float uu = s_u[tid], tt = s_t[tid], bb = s_b[tid];
        p = uu * tt + tt * bb + uu * bb + 0.5f * bb * bb;
    }
    s_red[tid] = p;
    __syncthreads();
    for (int s = FIN_TPB / 2; s > 0; s >>= 1) {
        if (tid < s) s_red[tid] += s_red[tid + s];
        __syncthreads();
    }

    if (tid == 0) {
        float y = w0[0] + bias + s_red[0] - 0.5f * sum_b_sq;
        float z = y * delta[0];
        float r = 1.f / (1.f + expf(-z));
        for (int i = 0; i < out_size; ++i) out[i] = r;
        g_nnz = 0;  // reset for next graph replay
    }
}

extern "C" void kernel_launch(void* const* d_in, const int* in_sizes, int n_in,
                              void* d_out, int out_size)
{
    const float* x     = (const float*)d_in[0];
    const float* delta = (const float*)d_in[1];
    /* pmi = d_in[2] unused */
    const float* w0    = (const float*)d_in[3];
    const float* wb    = (const float*)d_in[4];
    const float* uV    = (const float*)d_in[5];
    const float* tV    = (const float*)d_in[6];
    const float* bV    = (const float*)d_in[7];

    int P  = in_sizes[0];
    int N  = in_sizes[5] / KDIM;
    int M  = in_sizes[6] / KDIM;
    int P4 = P / 4;
    int blocks = (P4 + SCAN_TPB - 1) / SCAN_TPB;

    bfm_scan_kernel<<<blocks, SCAN_TPB>>>(x, P4, P);
    bfm_finish_kernel<<<1, FIN_TPB>>>(w0, delta, wb, uV, tV, bV,
                                      (float*)d_out, out_size, N, M);
}

// round 3
// speedup vs baseline: 1.8175x; 1.0075x over previous
#include <cuda_runtime.h>
#include <math.h>

// ---------------------------------------------------------------------------
// BFM factorization-machine scoring, sparsity-aware, single fused kernel.
//   y = w0 + x.w_bias + u.t + t.b + 0.5*(b.b - sum_b_sq) + u.b ; out = sigmoid(y*delta)
// All blocks compact nonzeros of x; the last block to finish becomes the
// "finisher": rank-sorts the tiny list (determinism), gathers wb + embedding
// rows in ONE pass (all loads in flight, hot in L2), and reduces.
// ---------------------------------------------------------------------------

#define KDIM 64
#define TPB 512
#define SORT_CAP 2048

__device__ int   g_nnz  = 0;   // reset by finisher each replay
__device__ int   g_done = 0;   // reset by finisher each replay
__device__ int   g_idx[2100000];
__device__ float g_val[2100000];

__global__ void __launch_bounds__(TPB)
bfm_fused_kernel(const float* __restrict__ x,
                 const float* __restrict__ wb,
                 const float* __restrict__ w0,
                 const float* __restrict__ delta,
                 const float* __restrict__ uV,
                 const float* __restrict__ tV,
                 const float* __restrict__ bV,
                 float* __restrict__ out,
                 int out_size, int P4, int P, int N, int M, int nblocks)
{
    const int tid = threadIdx.x;

    // ---------------- phase 1: scan + compact ----------------
    int i = blockIdx.x * TPB + tid;
    if (i < P4) {
        float4 xv = reinterpret_cast<const float4*>(x)[i];
        int base = i * 4;
        if (xv.x != 0.f) { int p = atomicAdd(&g_nnz, 1); g_idx[p] = base + 0; g_val[p] = xv.x; }
        if (xv.y != 0.f) { int p = atomicAdd(&g_nnz, 1); g_idx[p] = base + 1; g_val[p] = xv.y; }
        if (xv.z != 0.f) { int p = atomicAdd(&g_nnz, 1); g_idx[p] = base + 2; g_val[p] = xv.z; }
        if (xv.w != 0.f) { int p = atomicAdd(&g_nnz, 1); g_idx[p] = base + 3; g_val[p] = xv.w; }
    }
    if (blockIdx.x == 0 && tid == 0) {
        for (int r = P4 * 4; r < P; ++r) {
            float xv = x[r];
            if (xv != 0.f) { int p = atomicAdd(&g_nnz, 1); g_idx[p] = r; g_val[p] = xv; }
        }
    }

    // make this thread's global writes visible gpu-wide, then block-sync
    __threadfence();
    __syncthreads();

    // ---------------- last-block election ----------------
    __shared__ int s_last;
    if (tid == 0) {
        int d = atomicAdd(&g_done, 1);
        s_last = (d == nblocks - 1);
    }
    __syncthreads();
    if (!s_last) return;
    __threadfence();  // acquire: see all other blocks' list writes

    // ---------------- phase 2: finisher (one block) ----------------
    __shared__ float sA[TPB], sB[TPB], sC[TPB];
    __shared__ int   s_ri[SORT_CAP];
    __shared__ float s_rv[SORT_CAP];
    __shared__ int   s_idx[SORT_CAP];
    __shared__ float s_val[SORT_CAP];

    const int nnz = g_nnz;
    const bool in_smem = (nnz <= SORT_CAP);

    if (in_smem) {
        for (int q = tid; q < nnz; q += TPB) { s_ri[q] = g_idx[q]; s_rv[q] = g_val[q]; }
        __syncthreads();
        // rank sort by index (indices unique -> ranks form a permutation)
        for (int q = tid; q < nnz; q += TPB) {
            int my = s_ri[q];
            int rank = 0;
            for (int j = 0; j < nnz; ++j) rank += (s_ri[j] < my);
            s_idx[rank] = my; s_val[rank] = s_rv[q];
        }
        __syncthreads();
    }

    // combined gather: embeddings (all lanes) + wb (k==0 lanes), one round-trip
    const int k  = tid & (KDIM - 1);
    const int g8 = tid >> 6;           // 0..7 row groups
    float au = 0.f, at_ = 0.f, ab = 0.f, absq = 0.f, bias_acc = 0.f;
    #pragma unroll 4
    for (int j = g8; j < nnz; j += 8) {
        int idx; float v;
        if (in_smem) { idx = s_idx[j]; v = s_val[j]; }
        else         { idx = g_idx[j]; v = g_val[j]; }
        if (k == 0) bias_acc += v * wb[idx];
        bool isU = idx < N;
        bool isT = !isU && (idx < N + M);
        bool isB = !isU && !isT;
        const float* p = isU ? (uV + (size_t)idx * KDIM)
                       : isT ? (tV + (size_t)(idx - N) * KDIM)
                             : (bV + (size_t)(idx - N - M) * KDIM);
        float e  = p[k];
        float ve = v * e;
        au   += isU ? ve : 0.f;
        at_  += isT ? ve : 0.f;
        ab   += isB ? ve : 0.f;
        absq += isB ? ve * e : 0.f;
    }
    __syncthreads();

    // fold round 1: u, t, b vectors (8 groups -> 64 lanes)
    sA[tid] = au; sB[tid] = at_; sC[tid] = ab;
    __syncthreads();
    float u = 0.f, t = 0.f, b = 0.f;
    if (tid < KDIM) {
        #pragma unroll
        for (int q = 0; q < 8; ++q) {
            u += sA[tid + 64 * q];
            t += sB[tid + 64 * q];
            b += sC[tid + 64 * q];
        }
    }
    __syncthreads();

    // fold round 2: absq + bias
    sA[tid] = absq; sB[tid] = bias_acc;
    __syncthreads();
    if (tid < KDIM) {
        float aq = 0.f, bi = 0.f;
        #pragma unroll
        for (int q = 0; q < 8; ++q) {
            aq += sA[tid + 64 * q];
            bi += sB[tid + 64 * q];
        }
        // per-lane contribution of all terms
        float lane = u * t + t * b + u * b + 0.5f * b * b - 0.5f * aq + bi;
        #pragma unroll
        for (int off = 16; off > 0; off >>= 1)
            lane += __shfl_down_sync(0xffffffffu, lane, off);
        if ((tid & 31) == 0) sC[tid >> 5] = lane;   // warp 0 -> sC[0], warp 1 -> sC[1]
    }
    __syncthreads();

    if (tid == 0) {
        float y = w0[0] + sC[0] + sC[1];
        float z = y * delta[0];
        float r = 1.f / (1.f + expf(-z));
        for (int q = 0; q < out_size; ++q) out[q] = r;
        g_nnz  = 0;   // reset for next graph replay
        g_done = 0;
    }
}

extern "C" void kernel_launch(void* const* d_in, const int* in_sizes, int n_in,
                              void* d_out, int out_size)
{
    const float* x     = (const float*)d_in[0];
    const float* delta = (const float*)d_in[1];
    /* pmi = d_in[2] unused */
    const float* w0    = (const float*)d_in[3];
    const float* wb    = (const float*)d_in[4];
    const float* uV    = (const float*)d_in[5];
    const float* tV    = (const float*)d_in[6];
    const float* bV    = (const float*)d_in[7];

    int P  = in_sizes[0];
    int N  = in_sizes[5] / KDIM;
    int M  = in_sizes[6] / KDIM;
    int P4 = P / 4;
    int blocks = (P4 + TPB - 1) / TPB;

    bfm_fused_kernel<<<blocks, TPB>>>(x, wb, w0, delta, uV, tV, bV,
                                      (float*)d_out, out_size, P4, P, N, M, blocks);
}